// round 6
// baseline (speedup 1.0000x reference)
#include <cuda_runtime.h>
#include <math.h>

// ---------------- problem constants ----------------
constexpr int   B_TOT  = 1000000;
constexpr int   SPIN   = 1000;
constexpr int   TRAIN  = 800000;
constexpr float ML     = 2.9086f;
constexpr float SL     = 1.898f;
constexpr float U1MAX  = 221.519f;

// chunked-scan parameters
constexpr int CHUNK   = 32;                   // steps per chunk
constexpr int WARMCH  = 2;                    // warm-up chunks (64 steps)
constexpr int NCH     = B_TOT / CHUNK;        // 31250 (exact)
constexpr int SBLK    = 128;                  // threads (=chunks) per block
constexpr int SGRID   = (NCH + SBLK - 1) / SBLK;   // 245

constexpr int RBLOCKS = 132;
__device__ double g_part[RBLOCKS][2];

// dynamic SMEM layout (bytes)
constexpr int SX_ELEMS = (SBLK + WARMCH) * (CHUNK + 1);   // float2
constexpr int SG_ELEMS = SBLK * (CHUNK + 1);              // float, per array
constexpr int SX_BYTES = SX_ELEMS * 8;                    // 34320
constexpr int SG_BYTES = SG_ELEMS * 4;                    // 16896
constexpr int SMEM_TOTAL = SX_BYTES + 4 * SG_BYTES;       // 101904

// ---------------- math helpers ----------------
__device__ __forceinline__ float tanha(float z) {
    float r;
    asm("tanh.approx.f32 %0, %1;" : "=f"(r) : "f"(z));
    return r;
}

struct P {
    float koo, coo;        // zo = koo*c + coo
    float kib, cib, kibu;  // zi = kib*c + (kibu*u1 + cib)
    float kol, col;        // zl = kol*u2 + col
    float hoo1, hol1;      // 0.5*oo1, 0.5*ol1
};

__device__ __forceinline__ P load_params(
    const float* cmean, const float* cstd,
    const float* wro, const float* wrl, const float* wrf,
    const float* b0o, const float* wb1o,
    const float* b0l, const float* wb2l,
    const float* wb1u, const float* b0u)
{
    P p;
    float mo = cmean[0];
    float inv_so = 1.0f / cstd[0];
    float eo = __expf(wro[0]);
    float el = __expf(wrl[0]);
    float ef = __expf(wrf[0]);
    float id = __fdividef(1.0f, eo + el + ef);
    p.hoo1 = 0.5f * eo * id;
    p.hol1 = 0.5f * el * id;
    float w1o = wb1o[0], w1u = wb1u[0], w2l = wb2l[0];
    p.koo  = 0.5f * w1o * inv_so;
    p.coo  = 0.5f * (b0o[0] - mo * inv_so * w1o);
    p.kib  = 0.5f * w1u * inv_so;
    p.cib  = 0.5f * (b0u[0] - mo * inv_so * w1u);
    p.kibu = 0.5f * w1u / U1MAX;
    p.kol  = 0.5f * w2l / SL;
    p.col  = 0.5f * (b0l[0] - (ML / SL) * w2l);
    return p;
}

// warm-up step (state only). chain: fma -> tanh -> fma -> fma.
__device__ __forceinline__ float step_c(float c, float u1, float u2, const P& p) {
    float hu1 = 0.5f * u1;
    float zib = fmaf(u1, p.kibu, p.cib);
    float zl  = fmaf(u2, p.kol, p.col);
    float ol  = fmaf(tanha(zl), p.hol1, p.hol1);
    float zo  = fmaf(c, p.koo, p.coo);
    float zi  = fmaf(c, p.kib, zib);
    float to  = tanha(zo);
    float ti  = tanha(zi);
    float hc  = p.hoo1 * c;
    float olc_c = ol * c;
    float L   = (c > 0.0f) ? fminf(olc_c, u2) : olc_c;
    float base = ((c - hc) + hu1) - L;
    return fmaf(-hu1, ti, fmaf(-hc, to, base));
}

// ---------------- kernel A: sum/sumsq partials over y_obs[SPIN:TRAIN] -----
__global__ __launch_bounds__(256) void reduce_k(const float* __restrict__ y) {
    const float4* y4 = reinterpret_cast<const float4*>(y + SPIN);
    const int n4 = (TRAIN - SPIN) / 4;
    double s = 0.0, s2 = 0.0;
    int stride = gridDim.x * blockDim.x;
    for (int i = blockIdx.x * blockDim.x + threadIdx.x; i < n4; i += stride) {
        float4 v = __ldg(y4 + i);
        double a = v.x, b = v.y, cc = v.z, d = v.w;
        s  += (a + b) + (cc + d);
        s2 += (a * a + b * b) + (cc * cc + d * d);
    }
    #pragma unroll
    for (int o = 16; o > 0; o >>= 1) {
        s  += __shfl_down_sync(0xffffffffu, s,  o);
        s2 += __shfl_down_sync(0xffffffffu, s2, o);
    }
    __shared__ double sh[2][8];
    int lane = threadIdx.x & 31, warp = threadIdx.x >> 5;
    if (lane == 0) { sh[0][warp] = s; sh[1][warp] = s2; }
    __syncthreads();
    if (warp == 0) {
        s  = (lane < 8) ? sh[0][lane] : 0.0;
        s2 = (lane < 8) ? sh[1][lane] : 0.0;
        #pragma unroll
        for (int o = 4; o > 0; o >>= 1) {
            s  += __shfl_down_sync(0xffffffffu, s,  o);
            s2 += __shfl_down_sync(0xffffffffu, s2, o);
        }
        if (lane == 0) { g_part[blockIdx.x][0] = s; g_part[blockIdx.x][1] = s2; }
    }
}

// ---------------- kernel B: fused scan + gates + all outputs --------------
__global__ __launch_bounds__(SBLK) void fused_k(
    const float4* __restrict__ x4,
    float* __restrict__ out,
    const int* __restrict__ time_lag_p,
    const float* cmean, const float* cstd,
    const float* wro, const float* wrl, const float* wrf,
    const float* b0o, const float* wb1o,
    const float* b0l, const float* wb2l,
    const float* wb1u, const float* b0u)
{
    extern __shared__ char smem_raw[];
    float2 (*sx)[CHUNK + 1]  = reinterpret_cast<float2(*)[CHUNK + 1]>(smem_raw);
    float  (*sc)[CHUNK + 1]  = reinterpret_cast<float(*)[CHUNK + 1]>(smem_raw + SX_BYTES);
    float  (*soo)[CHUNK + 1] = reinterpret_cast<float(*)[CHUNK + 1]>(smem_raw + SX_BYTES + SG_BYTES);
    float  (*sib)[CHUNK + 1] = reinterpret_cast<float(*)[CHUNK + 1]>(smem_raw + SX_BYTES + 2 * SG_BYTES);
    float  (*sol)[CHUNK + 1] = reinterpret_cast<float(*)[CHUNK + 1]>(smem_raw + SX_BYTES + 3 * SG_BYTES);
    __shared__ float s_os;

    const int tid = threadIdx.x;
    const int b0  = blockIdx.x * SBLK;
    const int base_t = (b0 - WARMCH) * CHUNK;

    // warp 0: fold reduction partials -> obsstd (ddof=1)
    if (tid < 32) {
        double s = 0.0, s2 = 0.0;
        for (int i = tid; i < RBLOCKS; i += 32) {
            s  += g_part[i][0];
            s2 += g_part[i][1];
        }
        #pragma unroll
        for (int o = 16; o > 0; o >>= 1) {
            s  += __shfl_down_sync(0xffffffffu, s,  o);
            s2 += __shfl_down_sync(0xffffffffu, s2, o);
        }
        if (tid == 0) {
            double n = (double)(TRAIN - SPIN);
            s_os = (float)sqrt((s2 - s * s / n) / (n - 1.0));
        }
    }

    const P p = load_params(cmean, cstd, wro, wrl, wrf, b0o, wb1o, b0l, wb2l, wb1u, b0u);

    // ---- stage input window ----
    constexpr int NLD4 = (SBLK + WARMCH) * CHUNK / 2;   // 2080
    #pragma unroll 4
    for (int i = tid; i < NLD4; i += SBLK) {
        int t = base_t + 2 * i;
        float4 v = make_float4(0.f, 0.f, 0.f, 0.f);
        if (t >= 0 && t < B_TOT) v = __ldg(x4 + (t >> 1));
        int li = 2 * i;
        int row = li >> 5, s = li & 31;
        sx[row][s]     = make_float2(v.x, v.y);
        sx[row][s + 1] = make_float2(v.z, v.w);
    }
    __syncthreads();

    // ---- recurrence ----
    const int chunk = b0 + tid;
    const int row   = tid + WARMCH;
    float c = 0.0f;
    if (chunk < NCH) {
        #pragma unroll
        for (int d = WARMCH; d >= 1; --d) {
            if (chunk - d >= 0) {
                #pragma unroll 8
                for (int s = 0; s < CHUNK; ++s) {
                    float2 u = sx[row - d][s];
                    c = step_c(c, u.x, u.y, p);
                }
            }
        }
        #pragma unroll 4
        for (int s = 0; s < CHUNK; ++s) {
            float2 u = sx[row][s];
            // expanded step: same math as step_c, plus gate capture
            float hu1 = 0.5f * u.x;
            float zib = fmaf(u.x, p.kibu, p.cib);
            float zl  = fmaf(u.y, p.kol, p.col);
            float ol  = fmaf(tanha(zl), p.hol1, p.hol1);
            float zo  = fmaf(c, p.koo, p.coo);
            float zi  = fmaf(c, p.kib, zib);
            float to  = tanha(zo);
            float ti  = tanha(zi);
            float hc  = p.hoo1 * c;
            float olc_c = ol * c;
            float L   = (c > 0.0f) ? fminf(olc_c, u.y) : olc_c;
            float base = ((c - hc) + hu1) - L;
            sc[tid][s]  = c;                              // pre-update state
            soo[tid][s] = fmaf(to, p.hoo1, p.hoo1);
            sib[tid][s] = fmaf(ti, 0.5f, 0.5f);
            sol[tid][s] = ol;
            c = fmaf(-hu1, ti, fmaf(-hc, to, base));
        }
    }
    __syncthreads();

    // ---- write sweep: 4 consecutive timesteps per thread per iteration ----
    const int tl = time_lag_p[0];
    const float os = s_os;
    const size_t B = (size_t)B_TOT;
    const int t0 = b0 * CHUNK;

    for (int j = 0; j < (SBLK * CHUNK) / (SBLK * 4); ++j) {   // 8 iterations
        int i = j * (SBLK * 4) + tid * 4;
        int t = t0 + i;
        if (t >= B_TOT) continue;
        int r = i >> 5, s0 = i & 31;

        float4 vh, vc, vl, vlc, vbp, vib, voo, vol, volc, vf, vos;
        float4 hn0, hn1;
        float* ph = &vh.x;  float* pc = &vc.x;  float* pl = &vl.x;  float* plc = &vlc.x;
        float* pbp = &vbp.x; float* pib = &vib.x; float* poo = &voo.x;
        float* pol = &vol.x; float* polc = &volc.x; float* pf = &vf.x; float* pos = &vos.x;

        #pragma unroll
        for (int k = 0; k < 4; ++k) {
            float cv = sc[r][s0 + k];
            float2 u = sx[r + WARMCH][s0 + k];
            float oo = soo[r][s0 + k];
            float ib = sib[r][s0 + k];
            float ol = sol[r][s0 + k];
            float m  = (t + k >= tl) ? 1.0f : 0.0f;
            bool  pos_c = (cv > 0.0f);
            float olc  = pos_c ? fminf(ol, __fdividef(u.y, cv)) : ol;
            float olcc = pos_c ? fminf(ol * cv, u.y) : ol * cv;
            float bp = ib * u.x;
            float h  = fmaf(oo, cv, bp);
            ph[k]   = m * h;
            pc[k]   = m * cv;
            pl[k]   = m * (ol * cv);
            plc[k]  = m * olcc;
            pbp[k]  = m * bp;
            pib[k]  = m * ib;
            poo[k]  = m * oo;
            pol[k]  = m * ol;
            polc[k] = m * olc;
            pf[k]   = m * (1.0f - oo - olc);
            pos[k]  = m * os;
        }
        hn0 = make_float4(ph[0], pos[0], ph[1], pos[1]);
        hn1 = make_float4(ph[2], pos[2], ph[3], pos[3]);

        *reinterpret_cast<float4*>(out + t)          = vh;
        *reinterpret_cast<float4*>(out + B + t)      = vc;
        *reinterpret_cast<float4*>(out + 2 * B + t)  = vl;
        *reinterpret_cast<float4*>(out + 3 * B + t)  = vlc;
        *reinterpret_cast<float4*>(out + 4 * B + t)  = vbp;
        *reinterpret_cast<float4*>(out + 5 * B + t)  = vib;
        *reinterpret_cast<float4*>(out + 6 * B + t)  = voo;
        *reinterpret_cast<float4*>(out + 7 * B + t)  = vol;
        *reinterpret_cast<float4*>(out + 8 * B + t)  = volc;
        *reinterpret_cast<float4*>(out + 9 * B + t)  = vf;
        *reinterpret_cast<float4*>(out + 10 * B + 2 * (size_t)t)     = hn0;
        *reinterpret_cast<float4*>(out + 10 * B + 2 * (size_t)t + 4) = hn1;
        *reinterpret_cast<float4*>(out + 12 * B + t) = vos;
    }
}

// ---------------- launch ----------------
extern "C" void kernel_launch(void* const* d_in, const int* in_sizes, int n_in,
                              void* d_out, int out_size) {
    const float4* x4    = (const float4*)d_in[0];
    const int*    tl    = (const int*)   d_in[2];
    const float*  y_obs = (const float*) d_in[3];
    const float*  cmean = (const float*) d_in[4];
    const float*  cstd  = (const float*) d_in[5];
    const float*  wro   = (const float*) d_in[6];
    const float*  wrl   = (const float*) d_in[7];
    const float*  wrf   = (const float*) d_in[8];
    const float*  b0o   = (const float*) d_in[9];
    const float*  wb1o  = (const float*) d_in[10];
    const float*  b0l   = (const float*) d_in[11];
    const float*  wb2l  = (const float*) d_in[12];
    const float*  wb1u  = (const float*) d_in[13];
    const float*  b0u   = (const float*) d_in[14];
    float* out = (float*)d_out;

    cudaFuncSetAttribute(fused_k, cudaFuncAttributeMaxDynamicSharedMemorySize,
                         SMEM_TOTAL);

    reduce_k<<<RBLOCKS, 256>>>(y_obs);

    fused_k<<<SGRID, SBLK, SMEM_TOTAL>>>(x4, out, tl,
        cmean, cstd, wro, wrl, wrf, b0o, wb1o, b0l, wb2l, wb1u, b0u);
}